// round 1
// baseline (speedup 1.0000x reference)
#include <cuda_runtime.h>
#include <cmath>

// ---------------------------------------------------------------------------
// Problem constants
// ---------------------------------------------------------------------------
#define N_OBJ   2048
#define N_REL   4096
#define DIMF    1024
#define OUT_CAT 512
#define OUT_NC  3072

// ---------------------------------------------------------------------------
// Scratch (device globals; allocation-free per harness rules)
// ---------------------------------------------------------------------------
__device__ float g_q [N_REL * OUT_NC];
__device__ float g_k [N_REL * OUT_NC];
__device__ float g_qv[N_REL * OUT_NC];
__device__ float g_kv[N_REL * OUT_NC];
__device__ float g_S [6u * 2048u * 4096u];       // max score buffer (stage2)
__device__ float g_A10[N_OBJ * OUT_CAT];
__device__ float g_A20[N_OBJ * OUT_CAT];
__device__ float g_A11[N_OBJ * OUT_CAT];
__device__ float g_A21[N_REL * OUT_CAT];
__device__ float g_A12[N_REL * OUT_CAT];
__device__ float g_A22[N_OBJ * OUT_CAT];
__device__ float g_obj[N_OBJ * DIMF];
__device__ float g_rel[N_REL * DIMF];
__device__ float g_AH1[N_REL * OUT_NC];          // per-head a1 of mha4
__device__ float g_AH2[N_REL * OUT_NC];          // per-head a2 of mha3

// ---------------------------------------------------------------------------
// tf32 helpers
// ---------------------------------------------------------------------------
__device__ __forceinline__ float f2tf(float x) {
    unsigned u;
    asm("cvt.rna.tf32.f32 %0, %1;" : "=r"(u) : "f"(x));
    return __uint_as_float(u);
}

// ---------------------------------------------------------------------------
// Generic batched tf32 GEMM:  C = op(acc)  where acc = A·B (logical MxK * KxN)
//   TA=false: A(i,k) = A[i*lda + k]      TA=true:  A(i,k) = A[k*lda + i]
//   TB=false: B(k,j) = B[k*ldb + j]      TB=true:  B(k,j) = B[j*ldb + k]
//   MODE 0: C = acc*alpha + (bias ? bias[j] : 0)
//   MODE 1: C = elu(acc)
// Requirements (guaranteed by call sites): M,N multiples of 128; K multiple of
// 16; all leading dims & batch strides multiples of 4 (float4-aligned).
// ---------------------------------------------------------------------------
template<bool TA, bool TB, int MODE>
__global__ void __launch_bounds__(256)
gemm_tf32(const float* __restrict__ A, const float* __restrict__ B,
          float* __restrict__ C,
          int M, int N, int K, int lda, int ldb, int ldc,
          long long sA, long long sB, long long sC,
          const float* __restrict__ bias, float alpha)
{
    __shared__ float As[16][136];   // k-major, pad 8 -> conflict-free frag loads
    __shared__ float Bs[16][136];

    const int m0 = blockIdx.y * 128;
    const int n0 = blockIdx.x * 128;
    A += blockIdx.z * sA;
    B += blockIdx.z * sB;
    C += blockIdx.z * sC;

    const int tid  = threadIdx.x;
    const int warp = tid >> 5, lane = tid & 31;
    const int wm = warp >> 2, wn = warp & 3;     // 2 x 4 warp grid
    const int lq = lane >> 2, lr = lane & 3;

    float acc[4][4][4];
#pragma unroll
    for (int i = 0; i < 4; i++)
#pragma unroll
        for (int j = 0; j < 4; j++)
#pragma unroll
            for (int r = 0; r < 4; r++) acc[i][j][r] = 0.f;

    for (int k0 = 0; k0 < K; k0 += 16) {
        // ---- load A tile -> As[k][m] ----
        if (!TA) {
#pragma unroll
            for (int it = 0; it < 2; it++) {
                int idx = tid + it * 256;            // 0..511
                int r = idx >> 2, c = idx & 3;       // row 0..127, col-grp 0..3
                const float4 v = *(const float4*)(A + (long long)(m0 + r) * lda + k0 + c * 4);
                As[c * 4 + 0][r] = f2tf(v.x);
                As[c * 4 + 1][r] = f2tf(v.y);
                As[c * 4 + 2][r] = f2tf(v.z);
                As[c * 4 + 3][r] = f2tf(v.w);
            }
        } else {
#pragma unroll
            for (int it = 0; it < 2; it++) {
                int idx = tid + it * 256;
                int kk = idx >> 5, cm = idx & 31;    // k 0..15, m-grp 0..31
                const float4 v = *(const float4*)(A + (long long)(k0 + kk) * lda + m0 + cm * 4);
                As[kk][cm * 4 + 0] = f2tf(v.x);
                As[kk][cm * 4 + 1] = f2tf(v.y);
                As[kk][cm * 4 + 2] = f2tf(v.z);
                As[kk][cm * 4 + 3] = f2tf(v.w);
            }
        }
        // ---- load B tile -> Bs[k][n] ----
        if (!TB) {
#pragma unroll
            for (int it = 0; it < 2; it++) {
                int idx = tid + it * 256;
                int kk = idx >> 5, cn = idx & 31;
                const float4 v = *(const float4*)(B + (long long)(k0 + kk) * ldb + n0 + cn * 4);
                Bs[kk][cn * 4 + 0] = f2tf(v.x);
                Bs[kk][cn * 4 + 1] = f2tf(v.y);
                Bs[kk][cn * 4 + 2] = f2tf(v.z);
                Bs[kk][cn * 4 + 3] = f2tf(v.w);
            }
        } else {
#pragma unroll
            for (int it = 0; it < 2; it++) {
                int idx = tid + it * 256;
                int r = idx >> 2, c = idx & 3;       // n-row 0..127, k-grp 0..3
                const float4 v = *(const float4*)(B + (long long)(n0 + r) * ldb + k0 + c * 4);
                Bs[c * 4 + 0][r] = f2tf(v.x);
                Bs[c * 4 + 1][r] = f2tf(v.y);
                Bs[c * 4 + 2][r] = f2tf(v.z);
                Bs[c * 4 + 3][r] = f2tf(v.w);
            }
        }
        __syncthreads();

#pragma unroll
        for (int ks = 0; ks < 16; ks += 8) {
            unsigned a[4][4], b[4][2];
#pragma unroll
            for (int mt = 0; mt < 4; mt++) {
                int mb = wm * 64 + mt * 16 + lq;
                a[mt][0] = __float_as_uint(As[ks + lr    ][mb    ]);
                a[mt][1] = __float_as_uint(As[ks + lr    ][mb + 8]);
                a[mt][2] = __float_as_uint(As[ks + lr + 4][mb    ]);
                a[mt][3] = __float_as_uint(As[ks + lr + 4][mb + 8]);
            }
#pragma unroll
            for (int nt = 0; nt < 4; nt++) {
                int nb = wn * 32 + nt * 8 + lq;
                b[nt][0] = __float_as_uint(Bs[ks + lr    ][nb]);
                b[nt][1] = __float_as_uint(Bs[ks + lr + 4][nb]);
            }
#pragma unroll
            for (int mt = 0; mt < 4; mt++)
#pragma unroll
                for (int nt = 0; nt < 4; nt++) {
                    asm volatile(
                        "mma.sync.aligned.m16n8k8.row.col.f32.tf32.tf32.f32 "
                        "{%0,%1,%2,%3}, {%4,%5,%6,%7}, {%8,%9}, {%0,%1,%2,%3};"
                        : "+f"(acc[mt][nt][0]), "+f"(acc[mt][nt][1]),
                          "+f"(acc[mt][nt][2]), "+f"(acc[mt][nt][3])
                        : "r"(a[mt][0]), "r"(a[mt][1]), "r"(a[mt][2]), "r"(a[mt][3]),
                          "r"(b[nt][0]), "r"(b[nt][1]));
                }
        }
        __syncthreads();
    }

    // ---- epilogue ----
#pragma unroll
    for (int mt = 0; mt < 4; mt++) {
        int r0 = m0 + wm * 64 + mt * 16 + lq;
#pragma unroll
        for (int nt = 0; nt < 4; nt++) {
            int c0 = n0 + wn * 32 + nt * 8 + lr * 2;
            float v0 = acc[mt][nt][0], v1 = acc[mt][nt][1];
            float v2 = acc[mt][nt][2], v3 = acc[mt][nt][3];
            if (MODE == 0) {
                float b0 = bias ? bias[c0] : 0.f;
                float b1 = bias ? bias[c0 + 1] : 0.f;
                v0 = v0 * alpha + b0;  v1 = v1 * alpha + b1;
                v2 = v2 * alpha + b0;  v3 = v3 * alpha + b1;
            } else {
                v0 = v0 > 0.f ? v0 : (expf(v0) - 1.f);
                v1 = v1 > 0.f ? v1 : (expf(v1) - 1.f);
                v2 = v2 > 0.f ? v2 : (expf(v2) - 1.f);
                v3 = v3 > 0.f ? v3 : (expf(v3) - 1.f);
            }
            *(float2*)(C + (long long)r0 * ldc + c0)       = make_float2(v0, v1);
            *(float2*)(C + (long long)(r0 + 8) * ldc + c0) = make_float2(v2, v3);
        }
    }
}

// ---------------------------------------------------------------------------
// Row softmax, register-resident. ncols = NPER*256. One block per row.
// mask_diag: skip column (row % M) (implements the 1-eye mask).
// ---------------------------------------------------------------------------
template<int NPER>
__global__ void __launch_bounds__(256)
softmax_k(float* __restrict__ S, int mask_diag, int M)
{
    const int ncols = NPER * 256;
    const long long row = blockIdx.x;
    float* p = S + row * (long long)ncols;
    const int diag = mask_diag ? (int)(row % M) : -1;
    const int tid = threadIdx.x, warp = tid >> 5, lane = tid & 31;

    __shared__ float red[8];

    float v[NPER];
    float mx = -1e30f;
#pragma unroll
    for (int i = 0; i < NPER; i++) {
        int c = tid + i * 256;
        float x = p[c];
        if (c == diag) x = -1e30f;
        v[i] = x;
        mx = fmaxf(mx, x);
    }
#pragma unroll
    for (int o = 16; o; o >>= 1) mx = fmaxf(mx, __shfl_xor_sync(0xffffffffu, mx, o));
    if (lane == 0) red[warp] = mx;
    __syncthreads();
    mx = red[0];
#pragma unroll
    for (int i = 1; i < 8; i++) mx = fmaxf(mx, red[i]);

    float sm = 0.f;
#pragma unroll
    for (int i = 0; i < NPER; i++) { v[i] = __expf(v[i] - mx); sm += v[i]; }
#pragma unroll
    for (int o = 16; o; o >>= 1) sm += __shfl_xor_sync(0xffffffffu, sm, o);
    __syncthreads();
    if (lane == 0) red[warp] = sm;
    __syncthreads();
    sm = red[0];
#pragma unroll
    for (int i = 1; i < 8; i++) sm += red[i];

    const float inv = 1.f / sm;
#pragma unroll
    for (int i = 0; i < NPER; i++) p[tid + i * 256] = v[i] * inv;
}

// ---------------------------------------------------------------------------
// Elementwise combine kernels
// ---------------------------------------------------------------------------
__global__ void combine_obj_k(const float* __restrict__ fo,
                              const float* __restrict__ a, const float* __restrict__ b,
                              const float* __restrict__ c, const float* __restrict__ d,
                              float* __restrict__ obj, float* __restrict__ out)
{
    int i = blockIdx.x * 256 + threadIdx.x;        // N_OBJ*1024 threads
    int n = i >> 10, col = i & 1023;
    int cc = col & 511;
    float x1 = (col < 512) ? a[n * 512 + cc] : b[n * 512 + cc];
    float x2 = (col < 512) ? c[n * 512 + cc] : d[n * 512 + cc];
    float v = (fo[i] + x1 + x2) * (1.f / 3.f);
    obj[i] = v;
    out[i] = v;
}

__global__ void combine_rel_k(const float* __restrict__ fr,
                              const float* __restrict__ a, const float* __restrict__ b,
                              float* __restrict__ rel)
{
    int i = blockIdx.x * 256 + threadIdx.x;        // N_REL*1024 threads
    int n = i >> 10, col = i & 1023;
    int cc = col & 511;
    float x = (col < 512) ? a[n * 512 + cc] : b[n * 512 + cc];
    rel[i] = (fr[i] + x) * 0.5f;
}

__global__ void final_rel_k(const float* __restrict__ fr,
                            const float* __restrict__ AH1,  // a1 heads of mha4
                            const float* __restrict__ AH2,  // a2 heads of mha3
                            float* __restrict__ out)
{
    int i = blockIdx.x * 256 + threadIdx.x;        // N_REL*1024 threads
    int n = i >> 10, col = i & 1023;
    int cc = col & 511;
    const float* src = (col < 512) ? AH1 : AH2;
    float s = 0.f;
#pragma unroll
    for (int h = 0; h < 6; h++) s += src[(long long)n * 3072 + h * 512 + cc];
    out[i] = (fr[i] + s) * 0.5f;
}

// ---------------------------------------------------------------------------
// Host-side dispatch
// ---------------------------------------------------------------------------
static void gemm(bool ta, bool tb, int mode,
                 const float* A, const float* B, float* C,
                 int M, int N, int K, int lda, int ldb, int ldc,
                 long long sA, long long sB, long long sC, int batch,
                 const float* bias, float alpha)
{
    dim3 g(N / 128, M / 128, batch), blk(256);
    if (!ta && !tb) {
        if (mode == 0) gemm_tf32<false, false, 0><<<g, blk>>>(A, B, C, M, N, K, lda, ldb, ldc, sA, sB, sC, bias, alpha);
        else           gemm_tf32<false, false, 1><<<g, blk>>>(A, B, C, M, N, K, lda, ldb, ldc, sA, sB, sC, bias, alpha);
    } else if (!ta && tb) {
        if (mode == 0) gemm_tf32<false, true, 0><<<g, blk>>>(A, B, C, M, N, K, lda, ldb, ldc, sA, sB, sC, bias, alpha);
        else           gemm_tf32<false, true, 1><<<g, blk>>>(A, B, C, M, N, K, lda, ldb, ldc, sA, sB, sC, bias, alpha);
    } else {
        if (mode == 0) gemm_tf32<true, false, 0><<<g, blk>>>(A, B, C, M, N, K, lda, ldb, ldc, sA, sB, sC, bias, alpha);
        else           gemm_tf32<true, false, 1><<<g, blk>>>(A, B, C, M, N, K, lda, ldb, ldc, sA, sB, sC, bias, alpha);
    }
}

extern "C" void kernel_launch(void* const* d_in, const int* in_sizes, int n_in,
                              void* d_out, int out_size)
{
    (void)in_sizes; (void)n_in; (void)out_size;
    const float* fo = (const float*)d_in[0];
    const float* fr = (const float*)d_in[1];
    const float* Wc = (const float*)d_in[2];   // [3,4,1024,512]
    const float* bc = (const float*)d_in[3];   // [3,4,512]
    const float* Wo = (const float*)d_in[4];   // [2,4,1024,3072]
    const float* bo = (const float*)d_in[5];   // [2,4,3072]
    float* out = (float*)d_out;

    float *q, *k, *qv, *kv, *S, *A10, *A20, *A11, *A21, *A12, *A22, *obj, *rel, *AH1, *AH2;
    cudaGetSymbolAddress((void**)&q,   g_q);
    cudaGetSymbolAddress((void**)&k,   g_k);
    cudaGetSymbolAddress((void**)&qv,  g_qv);
    cudaGetSymbolAddress((void**)&kv,  g_kv);
    cudaGetSymbolAddress((void**)&S,   g_S);
    cudaGetSymbolAddress((void**)&A10, g_A10);
    cudaGetSymbolAddress((void**)&A20, g_A20);
    cudaGetSymbolAddress((void**)&A11, g_A11);
    cudaGetSymbolAddress((void**)&A21, g_A21);
    cudaGetSymbolAddress((void**)&A12, g_A12);
    cudaGetSymbolAddress((void**)&A22, g_A22);
    cudaGetSymbolAddress((void**)&obj, g_obj);
    cudaGetSymbolAddress((void**)&rel, g_rel);
    cudaGetSymbolAddress((void**)&AH1, g_AH1);
    cudaGetSymbolAddress((void**)&AH2, g_AH2);

    const long long WSc = 1024LL * 512, WSo = 1024LL * 3072;
    const float a128 = 1.f / sqrtf(128.f);
    const float a512 = 1.f / sqrtf(512.f);

    auto proj = [&](const float* X, int M, const float* W, const float* b,
                    int outd, float* dst) {
        gemm(false, false, 0, X, W, dst, M, outd, 1024, 1024, outd, outd,
             0, 0, 0, 1, b, 1.f);
    };

    // ================= Stage 1 =================
    // ---- mha0: xq=xk=feat_obj, mask=1-eye ----
    proj(fo, N_OBJ, Wc + 0 * WSc, bc + 0 * 512, OUT_CAT, q);
    proj(fo, N_OBJ, Wc + 1 * WSc, bc + 1 * 512, OUT_CAT, k);
    proj(fo, N_OBJ, Wc + 2 * WSc, bc + 2 * 512, OUT_CAT, qv);
    proj(fo, N_OBJ, Wc + 3 * WSc, bc + 3 * 512, OUT_CAT, kv);
    gemm(false, true, 0, q, k, S, 2048, 2048, 128, 512, 512, 2048,
         128, 128, 2048LL * 2048, 4, nullptr, a128);
    softmax_k<8><<<4 * 2048, 256>>>(S, 1, 2048);
    gemm(false, false, 1, S, kv, A10, 2048, 128, 2048, 2048, 512, 512,
         2048LL * 2048, 128, 128, 4, nullptr, 1.f);
    gemm(true, false, 1, S, qv, A20, 2048, 128, 2048, 2048, 512, 512,
         2048LL * 2048, 128, 128, 4, nullptr, 1.f);

    // ---- mha1: xq=feat_obj, xk=feat_rel ----
    proj(fo, N_OBJ, Wc + 4 * WSc, bc + 4 * 512, OUT_CAT, q);
    proj(fr, N_REL, Wc + 5 * WSc, bc + 5 * 512, OUT_CAT, k);
    proj(fo, N_OBJ, Wc + 6 * WSc, bc + 6 * 512, OUT_CAT, qv);
    proj(fr, N_REL, Wc + 7 * WSc, bc + 7 * 512, OUT_CAT, kv);
    gemm(false, true, 0, q, k, S, 2048, 4096, 128, 512, 512, 4096,
         128, 128, 2048LL * 4096, 4, nullptr, a128);
    softmax_k<16><<<4 * 2048, 256>>>(S, 0, 2048);
    gemm(false, false, 1, S, kv, A11, 2048, 128, 4096, 4096, 512, 512,
         2048LL * 4096, 128, 128, 4, nullptr, 1.f);
    gemm(true, false, 1, S, qv, A21, 4096, 128, 2048, 4096, 512, 512,
         2048LL * 4096, 128, 128, 4, nullptr, 1.f);

    // ---- mha2: xq=feat_rel, xk=feat_obj ----
    proj(fr, N_REL, Wc + 8 * WSc, bc + 8 * 512, OUT_CAT, q);
    proj(fo, N_OBJ, Wc + 9 * WSc, bc + 9 * 512, OUT_CAT, k);
    proj(fr, N_REL, Wc + 10 * WSc, bc + 10 * 512, OUT_CAT, qv);
    proj(fo, N_OBJ, Wc + 11 * WSc, bc + 11 * 512, OUT_CAT, kv);
    gemm(false, true, 0, q, k, S, 4096, 2048, 128, 512, 512, 2048,
         128, 128, 4096LL * 2048, 4, nullptr, a128);
    softmax_k<8><<<4 * 4096, 256>>>(S, 0, 4096);
    gemm(false, false, 1, S, kv, A12, 4096, 128, 2048, 2048, 512, 512,
         4096LL * 2048, 128, 128, 4, nullptr, 1.f);
    gemm(true, false, 1, S, qv, A22, 2048, 128, 4096, 2048, 512, 512,
         4096LL * 2048, 128, 128, 4, nullptr, 1.f);

    combine_obj_k<<<(N_OBJ * DIMF) / 256, 256>>>(fo, A10, A20, A11, A22, obj, out);
    combine_rel_k<<<(N_REL * DIMF) / 256, 256>>>(fr, A12, A21, rel);

    // ================= Stage 2 =================
    // ---- mha3: xq=obj_feat(2048), xk=rel_feat(4096); only a2 used ----
    proj(obj, N_OBJ, Wo + 0 * WSo, bo + 0 * 3072, OUT_NC, q);
    proj(rel, N_REL, Wo + 1 * WSo, bo + 1 * 3072, OUT_NC, k);
    proj(obj, N_OBJ, Wo + 2 * WSo, bo + 2 * 3072, OUT_NC, qv);   // kv unused
    gemm(false, true, 0, q, k, S, 2048, 4096, 512, 3072, 3072, 4096,
         512, 512, 2048LL * 4096, 6, nullptr, a512);
    softmax_k<16><<<6 * 2048, 256>>>(S, 0, 2048);
    gemm(true, false, 1, S, qv, AH2, 4096, 512, 2048, 4096, 3072, 3072,
         2048LL * 4096, 512, 512, 6, nullptr, 1.f);

    // ---- mha4: xq=rel_feat(4096), xk=obj_feat(2048); only a1 used ----
    proj(rel, N_REL, Wo + 4 * WSo, bo + 4 * 3072, OUT_NC, q);
    proj(obj, N_OBJ, Wo + 5 * WSo, bo + 5 * 3072, OUT_NC, k);
    proj(obj, N_OBJ, Wo + 7 * WSo, bo + 7 * 3072, OUT_NC, kv);   // qv unused
    gemm(false, true, 0, q, k, S, 4096, 2048, 512, 3072, 3072, 2048,
         512, 512, 4096LL * 2048, 6, nullptr, a512);
    softmax_k<8><<<6 * 4096, 256>>>(S, 0, 4096);
    gemm(false, false, 1, S, kv, AH1, 4096, 512, 2048, 2048, 3072, 3072,
         4096LL * 2048, 512, 512, 6, nullptr, 1.f);

    final_rel_k<<<(N_REL * DIMF) / 256, 256>>>(fr, AH1, AH2, out + (long long)N_OBJ * DIMF);
}

// round 2
// speedup vs baseline: 1.8767x; 1.8767x over previous
#include <cuda_runtime.h>
#include <cmath>

#define N_OBJ   2048
#define N_REL   4096
#define DIMF    1024

// ---------------------------------------------------------------------------
// Scratch (device globals)
// ---------------------------------------------------------------------------
__device__ float g_P1[12u * 4096u * 512u];          // stage-1 projections (12 slots)
__device__ float g_S [83886080u];                    // S0(16M) S1(32M) S2(32M) fl; stage2 reuses
__device__ float g_q3 [2048u * 3072u];
__device__ float g_k3 [4096u * 3072u];
__device__ float g_qv3[2048u * 3072u];
__device__ float g_q4 [4096u * 3072u];
__device__ float g_k4 [2048u * 3072u];
__device__ float g_kv4[2048u * 3072u];
__device__ float g_PA10[4u * 2048u * 512u];
__device__ float g_PA20[4u * 2048u * 512u];
__device__ float g_PA11[4u * 2048u * 512u];
__device__ float g_PA22[4u * 2048u * 512u];
__device__ float g_PA12[4u * 4096u * 512u];
__device__ float g_PA21[4u * 4096u * 512u];
__device__ float g_AH1[4096u * 3072u];
__device__ float g_AH2[4096u * 3072u];
__device__ float g_obj[2048u * 1024u];
__device__ float g_rel[4096u * 1024u];

// ---------------------------------------------------------------------------
// cp.async helpers
// ---------------------------------------------------------------------------
__device__ __forceinline__ void cpa16(float* s, const float* g) {
    unsigned a = (unsigned)__cvta_generic_to_shared(s);
    asm volatile("cp.async.cg.shared.global [%0], [%1], 16;" :: "r"(a), "l"(g) : "memory");
}
__device__ __forceinline__ void cp_commit() {
    asm volatile("cp.async.commit_group;" ::: "memory");
}
__device__ __forceinline__ void cp_wait1() {
    asm volatile("cp.async.wait_group 1;" ::: "memory");
}

__device__ __forceinline__ float elup(float x) { return x > 0.f ? x : (__expf(x) - 1.f); }

// Smem layouts:
//  MK: [128 rows][20]   (m-major; rows = m or n, cols = k)  -> for row-major-in-k gmem
//  KM: [16 rows][136]   (k-major; rows = k, cols = m or n)  -> for row-major-in-mn gmem
// Both are conflict-free for the mma fragment access patterns below.
#define MK_SZ (128 * 20)
#define KM_SZ (16 * 136)

// A(i,k): T=false -> A[i*lda+k] (load to MK); T=true -> A[k*lda+i] (load to KM)
template<bool T>
__device__ __forceinline__ void loadA(float* dst, const float* A, int lda,
                                      int m0, int k0, int tid) {
    if (!T) {
#pragma unroll
        for (int it = 0; it < 2; it++) {
            int idx = tid + it * 256, r = idx >> 2, c = idx & 3;
            cpa16(dst + r * 20 + c * 4, A + (long long)(m0 + r) * lda + k0 + c * 4);
        }
    } else {
#pragma unroll
        for (int it = 0; it < 2; it++) {
            int idx = tid + it * 256, kk = idx >> 5, cm = idx & 31;
            cpa16(dst + kk * 136 + cm * 4, A + (long long)(k0 + kk) * lda + m0 + cm * 4);
        }
    }
}
// B(k,j): T=false -> B[k*ldb+j] (KM); T=true -> B[j*ldb+k] (MK)
template<bool T>
__device__ __forceinline__ void loadB(float* dst, const float* B, int ldb,
                                      int n0, int k0, int tid) {
    if (!T) {
#pragma unroll
        for (int it = 0; it < 2; it++) {
            int idx = tid + it * 256, kk = idx >> 5, cn = idx & 31;
            cpa16(dst + kk * 136 + cn * 4, B + (long long)(k0 + kk) * ldb + n0 + cn * 4);
        }
    } else {
#pragma unroll
        for (int it = 0; it < 2; it++) {
            int idx = tid + it * 256, r = idx >> 2, c = idx & 3;
            cpa16(dst + r * 20 + c * 4, B + (long long)(n0 + r) * ldb + k0 + c * 4);
        }
    }
}

template<bool TA, bool TB>
__device__ __forceinline__ void mma16(const float* a_s, const float* b_s,
                                      float (&acc)[4][4][4],
                                      int wm, int wn, int lq, int lr) {
#pragma unroll
    for (int ks = 0; ks < 16; ks += 8) {
        unsigned af[4][4], bf[4][2];
#pragma unroll
        for (int mt = 0; mt < 4; mt++) {
            int mb = wm * 64 + mt * 16 + lq;
            if (TA) {
                af[mt][0] = __float_as_uint(a_s[(ks + lr) * 136 + mb]);
                af[mt][1] = __float_as_uint(a_s[(ks + lr) * 136 + mb + 8]);
                af[mt][2] = __float_as_uint(a_s[(ks + lr + 4) * 136 + mb]);
                af[mt][3] = __float_as_uint(a_s[(ks + lr + 4) * 136 + mb + 8]);
            } else {
                af[mt][0] = __float_as_uint(a_s[mb * 20 + ks + lr]);
                af[mt][1] = __float_as_uint(a_s[(mb + 8) * 20 + ks + lr]);
                af[mt][2] = __float_as_uint(a_s[mb * 20 + ks + lr + 4]);
                af[mt][3] = __float_as_uint(a_s[(mb + 8) * 20 + ks + lr + 4]);
            }
        }
#pragma unroll
        for (int nt = 0; nt < 4; nt++) {
            int nb = wn * 32 + nt * 8 + lq;
            if (!TB) {
                bf[nt][0] = __float_as_uint(b_s[(ks + lr) * 136 + nb]);
                bf[nt][1] = __float_as_uint(b_s[(ks + lr + 4) * 136 + nb]);
            } else {
                bf[nt][0] = __float_as_uint(b_s[nb * 20 + ks + lr]);
                bf[nt][1] = __float_as_uint(b_s[nb * 20 + ks + lr + 4]);
            }
        }
#pragma unroll
        for (int mt = 0; mt < 4; mt++)
#pragma unroll
            for (int nt = 0; nt < 4; nt++) {
                asm volatile(
                    "mma.sync.aligned.m16n8k8.row.col.f32.tf32.tf32.f32 "
                    "{%0,%1,%2,%3}, {%4,%5,%6,%7}, {%8,%9}, {%0,%1,%2,%3};"
                    : "+f"(acc[mt][nt][0]), "+f"(acc[mt][nt][1]),
                      "+f"(acc[mt][nt][2]), "+f"(acc[mt][nt][3])
                    : "r"(af[mt][0]), "r"(af[mt][1]), "r"(af[mt][2]), "r"(af[mt][3]),
                      "r"(bf[nt][0]), "r"(bf[nt][1]));
            }
    }
}

template<bool TA, bool TB>
__device__ __forceinline__ void mainloop(const float* A, const float* B,
                                         int K, int lda, int ldb, int m0, int n0,
                                         int tid, float* As, float* Bs,
                                         float (&acc)[4][4][4],
                                         int wm, int wn, int lq, int lr) {
    constexpr int AST = TA ? KM_SZ : MK_SZ;
    constexpr int BST = TB ? MK_SZ : KM_SZ;
    const int nk = K >> 4;
    loadA<TA>(As, A, lda, m0, 0, tid);
    loadB<TB>(Bs, B, ldb, n0, 0, tid);
    cp_commit();
    for (int kt = 0; kt < nk; kt++) {
        if (kt + 1 < nk) {
            loadA<TA>(As + ((kt + 1) & 1) * AST, A, lda, m0, (kt + 1) << 4, tid);
            loadB<TB>(Bs + ((kt + 1) & 1) * BST, B, ldb, n0, (kt + 1) << 4, tid);
        }
        cp_commit();
        cp_wait1();
        __syncthreads();
        mma16<TA, TB>(As + (kt & 1) * AST, Bs + (kt & 1) * BST, acc, wm, wn, lq, lr);
        __syncthreads();
    }
}

// ---------------------------------------------------------------------------
// Generic batched GEMM (+ optional K-split via z = s*nb + b)
//   MODE 0: C = acc*alpha    MODE 1: C = elu(acc)    MODE 2: C = acc (raw)
// ---------------------------------------------------------------------------
struct GArgs {
    const float *A, *B; float *C;
    int M, N, K, lda, ldb, ldc, nb;
    long long sA, sB, sC, sAk, sBk, sCk;
    float alpha;
};

template<bool TA, bool TB, int MODE>
__global__ void __launch_bounds__(256, 2) gemm_k(GArgs g)
{
    constexpr int AST = TA ? KM_SZ : MK_SZ;
    constexpr int BST = TB ? MK_SZ : KM_SZ;
    __shared__ float As[2 * AST];
    __shared__ float Bs[2 * BST];

    const int tid = threadIdx.x, warp = tid >> 5, lane = tid & 31;
    const int wm = warp >> 2, wn = warp & 3, lq = lane >> 2, lr = lane & 3;
    const int m0 = blockIdx.y * 128, n0 = blockIdx.x * 128;
    const int b = blockIdx.z % g.nb, s = blockIdx.z / g.nb;
    const float* A = g.A + b * g.sA + s * g.sAk;
    const float* B = g.B + b * g.sB + s * g.sBk;
    float* C = g.C + b * g.sC + s * g.sCk;

    float acc[4][4][4] = {};
    mainloop<TA, TB>(A, B, g.K, g.lda, g.ldb, m0, n0, tid, As, Bs, acc, wm, wn, lq, lr);

#pragma unroll
    for (int mt = 0; mt < 4; mt++) {
        int r0 = m0 + wm * 64 + mt * 16 + lq;
#pragma unroll
        for (int nt = 0; nt < 4; nt++) {
            int c0 = n0 + wn * 32 + nt * 8 + lr * 2;
            float v0 = acc[mt][nt][0], v1 = acc[mt][nt][1];
            float v2 = acc[mt][nt][2], v3 = acc[mt][nt][3];
            if (MODE == 0) { v0 *= g.alpha; v1 *= g.alpha; v2 *= g.alpha; v3 *= g.alpha; }
            if (MODE == 1) { v0 = elup(v0); v1 = elup(v1); v2 = elup(v2); v3 = elup(v3); }
            *(float2*)(C + (long long)r0 * g.ldc + c0)       = make_float2(v0, v1);
            *(float2*)(C + (long long)(r0 + 8) * g.ldc + c0) = make_float2(v2, v3);
        }
    }
}

// ---------------------------------------------------------------------------
// Pointer-batched projection GEMM: z selects {A, W, bias, C, M}; N,K uniform.
// ---------------------------------------------------------------------------
struct ProjB {
    const float* A[12]; const float* W[12]; const float* bias[12]; float* C[12];
    int M[12]; int N; int K;
};

__global__ void __launch_bounds__(256, 2) proj_k(ProjB pb)
{
    const int z = blockIdx.z;
    const int m0 = blockIdx.y * 128;
    if (m0 >= pb.M[z]) return;
    const int n0 = blockIdx.x * 128;

    __shared__ float As[2 * MK_SZ];
    __shared__ float Bs[2 * KM_SZ];

    const int tid = threadIdx.x, warp = tid >> 5, lane = tid & 31;
    const int wm = warp >> 2, wn = warp & 3, lq = lane >> 2, lr = lane & 3;

    float acc[4][4][4] = {};
    mainloop<false, false>(pb.A[z], pb.W[z], pb.K, pb.K, pb.N, m0, n0,
                           tid, As, Bs, acc, wm, wn, lq, lr);

    const float* bias = pb.bias[z];
    float* C = pb.C[z];
    const int ldc = pb.N;
#pragma unroll
    for (int mt = 0; mt < 4; mt++) {
        int r0 = m0 + wm * 64 + mt * 16 + lq;
#pragma unroll
        for (int nt = 0; nt < 4; nt++) {
            int c0 = n0 + wn * 32 + nt * 8 + lr * 2;
            float b0 = bias[c0], b1 = bias[c0 + 1];
            *(float2*)(C + (long long)r0 * ldc + c0) =
                make_float2(acc[mt][nt][0] + b0, acc[mt][nt][1] + b1);
            *(float2*)(C + (long long)(r0 + 8) * ldc + c0) =
                make_float2(acc[mt][nt][2] + b0, acc[mt][nt][3] + b1);
        }
    }
}

// ---------------------------------------------------------------------------
// Row softmax (register-resident); mask_diag skips column (row % M)
// ---------------------------------------------------------------------------
template<int NPER>
__global__ void __launch_bounds__(256) softmax_k(float* __restrict__ S, int mask_diag, int M)
{
    const int ncols = NPER * 256;
    const long long row = blockIdx.x;
    float* p = S + row * (long long)ncols;
    const int diag = mask_diag ? (int)(row % M) : -1;
    const int tid = threadIdx.x, warp = tid >> 5, lane = tid & 31;
    __shared__ float red[8];

    float v[NPER];
    float mx = -1e30f;
#pragma unroll
    for (int i = 0; i < NPER; i++) {
        int c = tid + i * 256;
        float x = p[c];
        if (c == diag) x = -1e30f;
        v[i] = x;
        mx = fmaxf(mx, x);
    }
#pragma unroll
    for (int o = 16; o; o >>= 1) mx = fmaxf(mx, __shfl_xor_sync(0xffffffffu, mx, o));
    if (lane == 0) red[warp] = mx;
    __syncthreads();
    mx = red[0];
#pragma unroll
    for (int i = 1; i < 8; i++) mx = fmaxf(mx, red[i]);

    float sm = 0.f;
#pragma unroll
    for (int i = 0; i < NPER; i++) { v[i] = __expf(v[i] - mx); sm += v[i]; }
#pragma unroll
    for (int o = 16; o; o >>= 1) sm += __shfl_xor_sync(0xffffffffu, sm, o);
    __syncthreads();
    if (lane == 0) red[warp] = sm;
    __syncthreads();
    sm = red[0];
#pragma unroll
    for (int i = 1; i < 8; i++) sm += red[i];

    const float inv = 1.f / sm;
#pragma unroll
    for (int i = 0; i < NPER; i++) p[tid + i * 256] = v[i] * inv;
}

// ---------------------------------------------------------------------------
// Combine kernels: sum 4 split-K partials, apply ELU, concat/residual
// ---------------------------------------------------------------------------
__global__ void combine_obj_k(const float* __restrict__ fo,
                              const float* __restrict__ pa, const float* __restrict__ pb,
                              const float* __restrict__ pc, const float* __restrict__ pd,
                              float* __restrict__ obj, float* __restrict__ out)
{
    const long long PS = 2048LL * 512;
    int i = blockIdx.x * 256 + threadIdx.x;
    int n = i >> 10, col = i & 1023, cc = col & 511;
    const float* P1 = (col < 512 ? pa : pb) + (long long)n * 512 + cc;
    const float* P2 = (col < 512 ? pc : pd) + (long long)n * 512 + cc;
    float s1 = 0.f, s2 = 0.f;
#pragma unroll
    for (int s = 0; s < 4; s++) { s1 += P1[s * PS]; s2 += P2[s * PS]; }
    float v = (fo[i] + elup(s1) + elup(s2)) * (1.f / 3.f);
    obj[i] = v;
    out[i] = v;
}

__global__ void combine_rel_k(const float* __restrict__ fr,
                              const float* __restrict__ pa, const float* __restrict__ pb,
                              float* __restrict__ rel)
{
    const long long PS = 4096LL * 512;
    int i = blockIdx.x * 256 + threadIdx.x;
    int n = i >> 10, col = i & 1023, cc = col & 511;
    const float* P = (col < 512 ? pa : pb) + (long long)n * 512 + cc;
    float s1 = 0.f;
#pragma unroll
    for (int s = 0; s < 4; s++) s1 += P[s * PS];
    rel[i] = (fr[i] + elup(s1)) * 0.5f;
}

__global__ void final_rel_k(const float* __restrict__ fr,
                            const float* __restrict__ AH1,
                            const float* __restrict__ AH2,
                            float* __restrict__ out)
{
    int i = blockIdx.x * 256 + threadIdx.x;
    int n = i >> 10, col = i & 1023, cc = col & 511;
    const float* src = (col < 512) ? AH1 : AH2;
    float s = 0.f;
#pragma unroll
    for (int h = 0; h < 6; h++) s += src[(long long)n * 3072 + h * 512 + cc];
    out[i] = (fr[i] + s) * 0.5f;
}

// ---------------------------------------------------------------------------
// Host
// ---------------------------------------------------------------------------
extern "C" void kernel_launch(void* const* d_in, const int* in_sizes, int n_in,
                              void* d_out, int out_size)
{
    (void)in_sizes; (void)n_in; (void)out_size;
    const float* fo = (const float*)d_in[0];
    const float* fr = (const float*)d_in[1];
    const float* Wc = (const float*)d_in[2];
    const float* bc = (const float*)d_in[3];
    const float* Wo = (const float*)d_in[4];
    const float* bo = (const float*)d_in[5];
    float* out = (float*)d_out;

    float *P1, *S, *q3, *k3, *qv3, *q4, *k4, *kv4;
    float *PA10, *PA20, *PA11, *PA22, *PA12, *PA21, *AH1, *AH2, *obj, *rel;
    cudaGetSymbolAddress((void**)&P1,   g_P1);
    cudaGetSymbolAddress((void**)&S,    g_S);
    cudaGetSymbolAddress((void**)&q3,   g_q3);
    cudaGetSymbolAddress((void**)&k3,   g_k3);
    cudaGetSymbolAddress((void**)&qv3,  g_qv3);
    cudaGetSymbolAddress((void**)&q4,   g_q4);
    cudaGetSymbolAddress((void**)&k4,   g_k4);
    cudaGetSymbolAddress((void**)&kv4,  g_kv4);
    cudaGetSymbolAddress((void**)&PA10, g_PA10);
    cudaGetSymbolAddress((void**)&PA20, g_PA20);
    cudaGetSymbolAddress((void**)&PA11, g_PA11);
    cudaGetSymbolAddress((void**)&PA22, g_PA22);
    cudaGetSymbolAddress((void**)&PA12, g_PA12);
    cudaGetSymbolAddress((void**)&PA21, g_PA21);
    cudaGetSymbolAddress((void**)&AH1,  g_AH1);
    cudaGetSymbolAddress((void**)&AH2,  g_AH2);
    cudaGetSymbolAddress((void**)&obj,  g_obj);
    cudaGetSymbolAddress((void**)&rel,  g_rel);

    float* S0 = S;
    float* S1 = S + 16777216;       // 4*2048*2048
    float* S2 = S1 + 33554432;      // 4*2048*4096

    const long long WSc = 1024LL * 512, WSo = 1024LL * 3072;
    const float a128 = 0.088388347648318447f;   // 1/sqrt(128)
    const float a512 = 0.044194173824159224f;   // 1/sqrt(512)

    auto P = [&](int s_) { return P1 + (long long)s_ * 4096 * 512; };

    // ================= Stage 1: all 12 projections in one launch =========
    {
        ProjB pb{};
        const float* src[12] = {fo,fo,fo,fo, fo,fr,fo,fr, fr,fo,fr,fo};
        int Ms[12] = {2048,2048,2048,2048, 2048,4096,2048,4096, 4096,2048,4096,2048};
        for (int z = 0; z < 12; z++) {
            pb.A[z] = src[z];
            pb.W[z] = Wc + z * WSc;
            pb.bias[z] = bc + z * 512;
            pb.C[z] = P(z);
            pb.M[z] = Ms[z];
        }
        pb.N = 512; pb.K = 1024;
        proj_k<<<dim3(4, 32, 12), 256>>>(pb);
    }

    GArgs g{};

    // ---- mha0 ----
    g = GArgs{P(0), P(1), S0, 2048, 2048, 128, 512, 512, 2048, 4,
              128, 128, 2048LL * 2048, 0, 0, 0, a128};
    gemm_k<false, true, 0><<<dim3(16, 16, 4), 256>>>(g);
    softmax_k<8><<<4 * 2048, 256>>>(S0, 1, 2048);
    g = GArgs{S0, P(3), PA10, 2048, 128, 512, 2048, 512, 512, 4,
              2048LL * 2048, 128, 128, 512, 512LL * 512, 2048LL * 512, 1.f};
    gemm_k<false, false, 2><<<dim3(1, 16, 16), 256>>>(g);
    g = GArgs{S0, P(2), PA20, 2048, 128, 512, 2048, 512, 512, 4,
              2048LL * 2048, 128, 128, 512LL * 2048, 512LL * 512, 2048LL * 512, 1.f};
    gemm_k<true, false, 2><<<dim3(1, 16, 16), 256>>>(g);

    // ---- mha1 ----
    g = GArgs{P(4), P(5), S1, 2048, 4096, 128, 512, 512, 4096, 4,
              128, 128, 2048LL * 4096, 0, 0, 0, a128};
    gemm_k<false, true, 0><<<dim3(32, 16, 4), 256>>>(g);
    softmax_k<16><<<4 * 2048, 256>>>(S1, 0, 2048);
    g = GArgs{S1, P(7), PA11, 2048, 128, 1024, 4096, 512, 512, 4,
              2048LL * 4096, 128, 128, 1024, 1024LL * 512, 2048LL * 512, 1.f};
    gemm_k<false, false, 2><<<dim3(1, 16, 16), 256>>>(g);
    g = GArgs{S1, P(6), PA21, 4096, 128, 512, 4096, 512, 512, 4,
              2048LL * 4096, 128, 128, 512LL * 4096, 512LL * 512, 4096LL * 512, 1.f};
    gemm_k<true, false, 2><<<dim3(1, 32, 16), 256>>>(g);

    // ---- mha2 ----
    g = GArgs{P(8), P(9), S2, 4096, 2048, 128, 512, 512, 2048, 4,
              128, 128, 4096LL * 2048, 0, 0, 0, a128};
    gemm_k<false, true, 0><<<dim3(16, 32, 4), 256>>>(g);
    softmax_k<8><<<4 * 4096, 256>>>(S2, 0, 4096);
    g = GArgs{S2, P(11), PA12, 4096, 128, 512, 2048, 512, 512, 4,
              4096LL * 2048, 128, 128, 512, 512LL * 512, 4096LL * 512, 1.f};
    gemm_k<false, false, 2><<<dim3(1, 32, 16), 256>>>(g);
    g = GArgs{S2, P(10), PA22, 2048, 128, 1024, 2048, 512, 512, 4,
              4096LL * 2048, 128, 128, 1024LL * 2048, 1024LL * 512, 2048LL * 512, 1.f};
    gemm_k<true, false, 2><<<dim3(1, 16, 16), 256>>>(g);

    combine_obj_k<<<(N_OBJ * DIMF) / 256, 256>>>(fo, PA10, PA20, PA11, PA22, obj, out);
    combine_rel_k<<<(N_REL * DIMF) / 256, 256>>>(fr, PA12, PA21, rel);

    // ================= Stage 2: 6 projections in one launch ==============
    {
        ProjB pb{};
        const float* src[6] = {obj, rel, obj, rel, obj, obj};
        int widx[6] = {0, 1, 2, 4, 5, 7};
        int Ms[6]   = {2048, 4096, 2048, 4096, 2048, 2048};
        float* dst[6] = {q3, k3, qv3, q4, k4, kv4};
        for (int z = 0; z < 6; z++) {
            pb.A[z] = src[z];
            pb.W[z] = Wo + (long long)widx[z] * WSo;
            pb.bias[z] = bo + widx[z] * 3072;
            pb.C[z] = dst[z];
            pb.M[z] = Ms[z];
        }
        pb.N = 3072; pb.K = 1024;
        proj_k<<<dim3(24, 32, 6), 256>>>(pb);
    }

    // ---- mha3 (only a2 used) ----
    g = GArgs{q3, k3, S, 2048, 4096, 512, 3072, 3072, 4096, 6,
              512, 512, 2048LL * 4096, 0, 0, 0, a512};
    gemm_k<false, true, 0><<<dim3(32, 16, 6), 256>>>(g);
    softmax_k<16><<<6 * 2048, 256>>>(S, 0, 2048);
    g = GArgs{S, qv3, AH2, 4096, 512, 2048, 4096, 3072, 3072, 6,
              2048LL * 4096, 512, 512, 0, 0, 0, 1.f};
    gemm_k<true, false, 1><<<dim3(4, 32, 6), 256>>>(g);

    // ---- mha4 (only a1 used) ----
    g = GArgs{q4, k4, S, 4096, 2048, 512, 3072, 3072, 2048, 6,
              512, 512, 4096LL * 2048, 0, 0, 0, a512};
    gemm_k<false, true, 0><<<dim3(16, 32, 6), 256>>>(g);
    softmax_k<8><<<6 * 4096, 256>>>(S, 0, 4096);
    g = GArgs{S, kv4, AH1, 4096, 512, 2048, 2048, 3072, 3072, 6,
              4096LL * 2048, 512, 512, 0, 0, 0, 1.f};
    gemm_k<false, false, 1><<<dim3(4, 32, 6), 256>>>(g);

    final_rel_k<<<(N_REL * DIMF) / 256, 256>>>(fr, AH1, AH2, out + (long long)N_OBJ * DIMF);
}

// round 7
// speedup vs baseline: 3.5215x; 1.8765x over previous
#include <cuda_runtime.h>
#include <cuda_bf16.h>
#include <cmath>

typedef __nv_bfloat16  bf16;
typedef __nv_bfloat162 bf162;

#define N_OBJ 2048
#define N_REL 4096
#define DIMF  1024

// ---------------------------------------------------------------------------
// Scratch (device globals)
// ---------------------------------------------------------------------------
__device__ bf16 g_bfo[2048u * 1024u];
__device__ bf16 g_bfr[4096u * 1024u];
__device__ bf16 g_bWc[12u * 1024u * 512u];
__device__ bf16 g_bWo[8u * 1024u * 3072u];
__device__ bf16 g_P1 [12u * 4096u * 512u];         // stage-1 projections
__device__ bf16 g_S  [83886080u];                  // S0|S1|S2 stage1; stage2 reuses
__device__ bf16 g_q3 [2048u * 3072u];
__device__ bf16 g_k3 [4096u * 3072u];
__device__ bf16 g_qv3[2048u * 3072u];
__device__ bf16 g_q4 [4096u * 3072u];
__device__ bf16 g_k4 [2048u * 3072u];
__device__ bf16 g_kv4[2048u * 3072u];
__device__ float g_PA10[4u * 2048u * 512u];
__device__ float g_PA20[4u * 2048u * 512u];
__device__ float g_PA11[4u * 2048u * 512u];
__device__ float g_PA22[4u * 2048u * 512u];
__device__ float g_PA12[4u * 4096u * 512u];
__device__ float g_PA21[4u * 4096u * 512u];
__device__ float g_AH1[4096u * 3072u];
__device__ float g_AH2[4096u * 3072u];
__device__ bf16  g_objb[2048u * 1024u];
__device__ bf16  g_relb[4096u * 1024u];

// ---------------------------------------------------------------------------
// Primitive helpers
// ---------------------------------------------------------------------------
__device__ __forceinline__ void cpa16(void* s, const void* g) {
    unsigned a = (unsigned)__cvta_generic_to_shared(s);
    asm volatile("cp.async.cg.shared.global [%0], [%1], 16;" :: "r"(a), "l"(g) : "memory");
}
__device__ __forceinline__ void cp_commit() { asm volatile("cp.async.commit_group;" ::: "memory"); }
__device__ __forceinline__ void cp_wait2()  { asm volatile("cp.async.wait_group 2;" ::: "memory"); }

__device__ __forceinline__ void ldmx4(unsigned& r0, unsigned& r1, unsigned& r2, unsigned& r3,
                                      const bf16* p) {
    unsigned a = (unsigned)__cvta_generic_to_shared(p);
    asm volatile("ldmatrix.sync.aligned.m8n8.x4.shared.b16 {%0,%1,%2,%3}, [%4];"
                 : "=r"(r0), "=r"(r1), "=r"(r2), "=r"(r3) : "r"(a));
}
__device__ __forceinline__ void ldmx4t(unsigned& r0, unsigned& r1, unsigned& r2, unsigned& r3,
                                       const bf16* p) {
    unsigned a = (unsigned)__cvta_generic_to_shared(p);
    asm volatile("ldmatrix.sync.aligned.m8n8.x4.trans.shared.b16 {%0,%1,%2,%3}, [%4];"
                 : "=r"(r0), "=r"(r1), "=r"(r2), "=r"(r3) : "r"(a));
}
__device__ __forceinline__ float elup(float x) { return x > 0.f ? x : (__expf(x) - 1.f); }

// Smem tile layouts (bf16 element counts):
//  natural: [128 rows][40]  (row = m or n, k contiguous), pad 40 -> conflict-free
//  k-major: [32 rows][136]  (row = k), pad 136 -> conflict-free (trans ldmatrix)
#define NAT_SZ (128 * 40)
#define KMJ_SZ (32 * 136)

// L=0: gmem row-major (row=m/n, k contig) -> natural; L=1: gmem [k][row] -> k-major
template<int L>
__device__ __forceinline__ void loadTile(bf16* dst, const bf16* src, int ld,
                                         int rb, int k0, int tid) {
    if (L == 0) {
#pragma unroll
        for (int it = 0; it < 2; it++) {
            int idx = tid + it * 256, rr = idx >> 2, c = idx & 3;
            cpa16(dst + rr * 40 + c * 8, src + (long long)(rb + rr) * ld + k0 + c * 8);
        }
    } else {
#pragma unroll
        for (int it = 0; it < 2; it++) {
            int idx = tid + it * 256, kk = idx >> 4, c = idx & 15;
            cpa16(dst + kk * 136 + c * 8, src + (long long)(k0 + kk) * ld + rb + c * 8);
        }
    }
}

// One BK=32 stage of mma over a 128x128 block tile (8 warps, 64x32 warp tiles)
template<int LA, int LB>
__device__ __forceinline__ void mma32(const bf16* As, const bf16* Bs,
                                      float (&acc)[4][4][4], int wm, int wn, int lane) {
    const int q = lane >> 3, r = lane & 7;
#pragma unroll
    for (int ks = 0; ks < 32; ks += 16) {
        unsigned af[4][4];
#pragma unroll
        for (int mt = 0; mt < 4; mt++) {
            int mb = wm * 64 + mt * 16;
            if (LA == 0)
                ldmx4(af[mt][0], af[mt][1], af[mt][2], af[mt][3],
                      As + (mb + (q & 1) * 8 + r) * 40 + ks + (q >> 1) * 8);
            else
                ldmx4t(af[mt][0], af[mt][1], af[mt][2], af[mt][3],
                       As + (ks + (q >> 1) * 8 + r) * 136 + mb + (q & 1) * 8);
        }
        unsigned bq[4][2];
#pragma unroll
        for (int pt = 0; pt < 2; pt++) {
            int nb = wn * 32 + pt * 16;
            unsigned b0, b1, b2, b3;
            if (LB == 0)
                ldmx4(b0, b1, b2, b3,
                      Bs + (nb + (q >> 1) * 8 + r) * 40 + ks + (q & 1) * 8);
            else
                ldmx4t(b0, b1, b2, b3,
                       Bs + (ks + (q & 1) * 8 + r) * 136 + nb + (q >> 1) * 8);
            bq[pt * 2][0] = b0; bq[pt * 2][1] = b1;
            bq[pt * 2 + 1][0] = b2; bq[pt * 2 + 1][1] = b3;
        }
#pragma unroll
        for (int mt = 0; mt < 4; mt++)
#pragma unroll
            for (int nt = 0; nt < 4; nt++)
                asm volatile(
                    "mma.sync.aligned.m16n8k16.row.col.f32.bf16.bf16.f32 "
                    "{%0,%1,%2,%3}, {%4,%5,%6,%7}, {%8,%9}, {%0,%1,%2,%3};"
                    : "+f"(acc[mt][nt][0]), "+f"(acc[mt][nt][1]),
                      "+f"(acc[mt][nt][2]), "+f"(acc[mt][nt][3])
                    : "r"(af[mt][0]), "r"(af[mt][1]), "r"(af[mt][2]), "r"(af[mt][3]),
                      "r"(bq[nt][0]), "r"(bq[nt][1]));
    }
}

// ---------------------------------------------------------------------------
// Generic batched GEMM. z = s*nb + b (split-K s, batch b).
//   MODE 0: C = acc*alpha   MODE 1: C = elu(acc)   MODE 2: raw
//   OB 0: fp32 out          OB 1: bf16 out
// ---------------------------------------------------------------------------
struct GArgs {
    const bf16 *A, *B; void* C;
    int M, N, K, lda, ldb, ldc, nb;
    long long sA, sB, sC, sAk, sBk, sCk;
    float alpha;
};

template<int LA, int LB, int MODE, int OB>
__global__ void __launch_bounds__(256, 2) gemm_k(GArgs g)
{
    constexpr int AST = LA ? KMJ_SZ : NAT_SZ;
    constexpr int BST = LB ? KMJ_SZ : NAT_SZ;
    extern __shared__ bf16 sm[];
    bf16* As = sm;
    bf16* Bs = sm + 3 * AST;

    const int tid = threadIdx.x, lane = tid & 31, warp = tid >> 5;
    const int wm = warp >> 2, wn = warp & 3, lq = lane >> 2, lr = lane & 3;
    const int m0 = blockIdx.y * 128, n0 = blockIdx.x * 128;
    const int b = blockIdx.z % g.nb, s = blockIdx.z / g.nb;
    const bf16* A = g.A + b * g.sA + s * g.sAk;
    const bf16* B = g.B + b * g.sB + s * g.sBk;

    float acc[4][4][4] = {};
    const int nk = g.K >> 5;

    loadTile<LA>(As, A, g.lda, m0, 0, tid);
    loadTile<LB>(Bs, B, g.ldb, n0, 0, tid);
    cp_commit();
    loadTile<LA>(As + AST, A, g.lda, m0, 32, tid);
    loadTile<LB>(Bs + BST, B, g.ldb, n0, 32, tid);
    cp_commit();

    for (int kt = 0; kt < nk; kt++) {
        if (kt + 2 < nk) {
            int buf = (kt + 2) % 3;
            loadTile<LA>(As + buf * AST, A, g.lda, m0, (kt + 2) * 32, tid);
            loadTile<LB>(Bs + buf * BST, B, g.ldb, n0, (kt + 2) * 32, tid);
        }
        cp_commit();
        cp_wait2();
        __syncthreads();
        mma32<LA, LB>(As + (kt % 3) * AST, Bs + (kt % 3) * BST, acc, wm, wn, lane);
        __syncthreads();
    }

#pragma unroll
    for (int mt = 0; mt < 4; mt++) {
        int r0 = m0 + wm * 64 + mt * 16 + lq;
#pragma unroll
        for (int nt = 0; nt < 4; nt++) {
            int c0 = n0 + wn * 32 + nt * 8 + lr * 2;
            float v0 = acc[mt][nt][0], v1 = acc[mt][nt][1];
            float v2 = acc[mt][nt][2], v3 = acc[mt][nt][3];
            if (MODE == 0) { v0 *= g.alpha; v1 *= g.alpha; v2 *= g.alpha; v3 *= g.alpha; }
            if (MODE == 1) { v0 = elup(v0); v1 = elup(v1); v2 = elup(v2); v3 = elup(v3); }
            long long o1 = (long long)r0 * g.ldc + c0;
            long long o2 = (long long)(r0 + 8) * g.ldc + c0;
            if (OB == 0) {
                float* C = (float*)g.C + b * g.sC + s * g.sCk;
                *(float2*)(C + o1) = make_float2(v0, v1);
                *(float2*)(C + o2) = make_float2(v2, v3);
            } else {
                bf16* C = (bf16*)g.C + b * g.sC + s * g.sCk;
                *(bf162*)(C + o1) = __floats2bfloat162_rn(v0, v1);
                *(bf162*)(C + o2) = __floats2bfloat162_rn(v2, v3);
            }
        }
    }
}

// ---------------------------------------------------------------------------
// Pointer-batched projection GEMM (LA=0, LB=1), bias fp32, bf16 out.
// ---------------------------------------------------------------------------
struct ProjB {
    const bf16* A[12]; const bf16* W[12]; const float* bias[12]; bf16* C[12];
    int M[12]; int N; int K;
};

__global__ void __launch_bounds__(256, 2) proj_k(ProjB pb)
{
    const int z = blockIdx.z;
    const int m0 = blockIdx.y * 128;
    if (m0 >= pb.M[z]) return;
    const int n0 = blockIdx.x * 128;

    extern __shared__ bf16 sm[];
    bf16* As = sm;
    bf16* Bs = sm + 3 * NAT_SZ;

    const int tid = threadIdx.x, lane = tid & 31, warp = tid >> 5;
    const int wm = warp >> 2, wn = warp & 3, lq = lane >> 2, lr = lane & 3;

    const bf16* A = pb.A[z];
    const bf16* W = pb.W[z];
    const int K = pb.K, N = pb.N;

    float acc[4][4][4] = {};
    const int nk = K >> 5;

    loadTile<0>(As, A, K, m0, 0, tid);
    loadTile<1>(Bs, W, N, n0, 0, tid);
    cp_commit();
    loadTile<0>(As + NAT_SZ, A, K, m0, 32, tid);
    loadTile<1>(Bs + KMJ_SZ, W, N, n0, 32, tid);
    cp_commit();

    for (int kt = 0; kt < nk; kt++) {
        if (kt + 2 < nk) {
            int buf = (kt + 2) % 3;
            loadTile<0>(As + buf * NAT_SZ, A, K, m0, (kt + 2) * 32, tid);
            loadTile<1>(Bs + buf * KMJ_SZ, W, N, n0, (kt + 2) * 32, tid);
        }
        cp_commit();
        cp_wait2();
        __syncthreads();
        mma32<0, 1>(As + (kt % 3) * NAT_SZ, Bs + (kt % 3) * KMJ_SZ, acc, wm, wn, lane);
        __syncthreads();
    }

    const float* bias = pb.bias[z];
    bf16* C = pb.C[z];
#pragma unroll
    for (int mt = 0; mt < 4; mt++) {
        int r0 = m0 + wm * 64 + mt * 16 + lq;
#pragma unroll
        for (int nt = 0; nt < 4; nt++) {
            int c0 = n0 + wn * 32 + nt * 8 + lr * 2;
            float b0 = bias[c0], b1 = bias[c0 + 1];
            *(bf162*)(C + (long long)r0 * N + c0) =
                __floats2bfloat162_rn(acc[mt][nt][0] + b0, acc[mt][nt][1] + b1);
            *(bf162*)(C + (long long)(r0 + 8) * N + c0) =
                __floats2bfloat162_rn(acc[mt][nt][2] + b0, acc[mt][nt][3] + b1);
        }
    }
}

// ---------------------------------------------------------------------------
// Softmax over bf16 scores (in-place). mask_diag skips column (row % M).
// ---------------------------------------------------------------------------
template<int NPER>
__global__ void __launch_bounds__(256) softmax_k(bf16* __restrict__ S, int mask_diag, int M)
{
    const int ncols = NPER * 256;
    const long long row = blockIdx.x;
    bf16* p = S + row * (long long)ncols;
    const int diag = mask_diag ? (int)(row % M) : -1;
    const int tid = threadIdx.x, warp = tid >> 5, lane = tid & 31;
    __shared__ float red[8];

    float v[NPER];
    float mx = -1e30f;
#pragma unroll
    for (int i = 0; i < NPER; i++) {
        int c = tid + i * 256;
        float x = __bfloat162float(p[c]);
        if (c == diag) x = -1e30f;
        v[i] = x;
        mx = fmaxf(mx, x);
    }
#pragma unroll
    for (int o = 16; o; o >>= 1) mx = fmaxf(mx, __shfl_xor_sync(0xffffffffu, mx, o));
    if (lane == 0) red[warp] = mx;
    __syncthreads();
    mx = red[0];
#pragma unroll
    for (int i = 1; i < 8; i++) mx = fmaxf(mx, red[i]);

    float sm = 0.f;
#pragma unroll
    for (int i = 0; i < NPER; i++) { v[i] = __expf(v[i] - mx); sm += v[i]; }
#pragma unroll
    for (int o = 16; o; o >>= 1) sm += __shfl_xor_sync(0xffffffffu, sm, o);
    __syncthreads();
    if (lane == 0) red[warp] = sm;
    __syncthreads();
    sm = red[0];
#pragma unroll
    for (int i = 1; i < 8; i++) sm += red[i];

    const float inv = 1.f / sm;
#pragma unroll
    for (int i = 0; i < NPER; i++) p[tid + i * 256] = __float2bfloat16(v[i] * inv);
}

// ---------------------------------------------------------------------------
// fp32 -> bf16 conversion (4 elts/thread)
// ---------------------------------------------------------------------------
__global__ void f2b_k(const float* __restrict__ s, bf16* __restrict__ d)
{
    long long i = ((long long)blockIdx.x * 256 + threadIdx.x) * 4;
    float4 v = *(const float4*)(s + i);
    *(bf162*)(d + i)     = __floats2bfloat162_rn(v.x, v.y);
    *(bf162*)(d + i + 2) = __floats2bfloat162_rn(v.z, v.w);
}

// ---------------------------------------------------------------------------
// Combine kernels
// ---------------------------------------------------------------------------
__global__ void combine_obj_k(const float* __restrict__ fo,
                              const float* __restrict__ pa, const float* __restrict__ pb,
                              const float* __restrict__ pc, const float* __restrict__ pd,
                              float* __restrict__ out, bf16* __restrict__ objb)
{
    const long long PS = 2048LL * 512;
    int i = blockIdx.x * 256 + threadIdx.x;
    int n = i >> 10, col = i & 1023, cc = col & 511;
    const float* P1 = (col < 512 ? pa : pb) + (long long)n * 512 + cc;
    const float* P2 = (col < 512 ? pc : pd) + (long long)n * 512 + cc;
    float s1 = 0.f, s2 = 0.f;
#pragma unroll
    for (int s = 0; s < 4; s++) { s1 += P1[s * PS]; s2 += P2[s * PS]; }
    float v = (fo[i] + elup(s1) + elup(s2)) * (1.f / 3.f);
    out[i]  = v;
    objb[i] = __float2bfloat16(v);
}

__global__ void combine_rel_k(const float* __restrict__ fr,
                              const float* __restrict__ pa, const float* __restrict__ pb,
                              bf16* __restrict__ relb)
{
    const long long PS = 4096LL * 512;
    int i = blockIdx.x * 256 + threadIdx.x;
    int n = i >> 10, col = i & 1023, cc = col & 511;
    const float* P = (col < 512 ? pa : pb) + (long long)n * 512 + cc;
    float s1 = 0.f;
#pragma unroll
    for (int s = 0; s < 4; s++) s1 += P[s * PS];
    relb[i] = __float2bfloat16((fr[i] + elup(s1)) * 0.5f);
}

__global__ void final_rel_k(const float* __restrict__ fr,
                            const float* __restrict__ AH1,
                            const float* __restrict__ AH2,
                            float* __restrict__ out)
{
    int i = blockIdx.x * 256 + threadIdx.x;
    int n = i >> 10, col = i & 1023, cc = col & 511;
    const float* src = (col < 512) ? AH1 : AH2;
    float s = 0.f;
#pragma unroll
    for (int h = 0; h < 6; h++) s += src[(long long)n * 3072 + h * 512 + cc];
    out[i] = (fr[i] + s) * 0.5f;
}

// ---------------------------------------------------------------------------
// Host
// ---------------------------------------------------------------------------
#define SM_00 (3 * (NAT_SZ + NAT_SZ) * 2)
#define SM_01 (3 * (NAT_SZ + KMJ_SZ) * 2)
#define SM_11 (3 * (KMJ_SZ + KMJ_SZ) * 2)

extern "C" void kernel_launch(void* const* d_in, const int* in_sizes, int n_in,
                              void* d_out, int out_size)
{
    (void)in_sizes; (void)n_in; (void)out_size;
    const float* fo = (const float*)d_in[0];
    const float* fr = (const float*)d_in[1];
    const float* Wc = (const float*)d_in[2];
    const float* bc = (const float*)d_in[3];
    const float* Wo = (const float*)d_in[4];
    const float* bo = (const float*)d_in[5];
    float* out = (float*)d_out;

    bf16 *bfo, *bfr, *bWc, *bWo, *P1, *S, *q3, *k3, *qv3, *q4, *k4, *kv4, *objb, *relb;
    float *PA10, *PA20, *PA11, *PA22, *PA12, *PA21, *AH1, *AH2;
    cudaGetSymbolAddress((void**)&bfo,  g_bfo);
    cudaGetSymbolAddress((void**)&bfr,  g_bfr);
    cudaGetSymbolAddress((void**)&bWc,  g_bWc);
    cudaGetSymbolAddress((void**)&bWo,  g_bWo);
    cudaGetSymbolAddress((void**)&P1,   g_P1);
    cudaGetSymbolAddress((void**)&S,    g_S);
    cudaGetSymbolAddress((void**)&q3,   g_q3);
    cudaGetSymbolAddress((void**)&k3,   g_k3);
    cudaGetSymbolAddress((void**)&qv3,  g_qv3);
    cudaGetSymbolAddress((void**)&q4,   g_q4);
    cudaGetSymbolAddress((void**)&k4,   g_k4);
    cudaGetSymbolAddress((void**)&kv4,  g_kv4);
    cudaGetSymbolAddress((void**)&objb, g_objb);
    cudaGetSymbolAddress((void**)&relb, g_relb);
    cudaGetSymbolAddress((void**)&PA10, g_PA10);
    cudaGetSymbolAddress((void**)&PA20, g_PA20);
    cudaGetSymbolAddress((void**)&PA11, g_PA11);
    cudaGetSymbolAddress((void**)&PA22, g_PA22);
    cudaGetSymbolAddress((void**)&PA12, g_PA12);
    cudaGetSymbolAddress((void**)&PA21, g_PA21);
    cudaGetSymbolAddress((void**)&AH1,  g_AH1);
    cudaGetSymbolAddress((void**)&AH2,  g_AH2);

    cudaFuncSetAttribute(proj_k,              cudaFuncAttributeMaxDynamicSharedMemorySize, SM_01);
    cudaFuncSetAttribute(gemm_k<0, 0, 0, 1>,  cudaFuncAttributeMaxDynamicSharedMemorySize, SM_00);
    cudaFuncSetAttribute(gemm_k<0, 1, 2, 0>,  cudaFuncAttributeMaxDynamicSharedMemorySize, SM_01);
    cudaFuncSetAttribute(gemm_k<1, 1, 2, 0>,  cudaFuncAttributeMaxDynamicSharedMemorySize, SM_11);
    cudaFuncSetAttribute(gemm_k<0, 1, 1, 0>,  cudaFuncAttributeMaxDynamicSharedMemorySize, SM_01);
    cudaFuncSetAttribute(gemm_k<1, 1, 1, 0>,  cudaFuncAttributeMaxDynamicSharedMemorySize, SM_11);

    bf16* S0 = S;
    bf16* S1 = S + 16777216;   // 4*2048*2048
    bf16* S2 = S1 + 33554432;  // 4*2048*4096

    const long long WSc = 1024LL * 512, WSo = 1024LL * 3072;
    const float a128 = 0.088388347648318447f;
    const float a512 = 0.044194173824159224f;
    auto P = [&](int s_) { return P1 + (long long)s_ * 4096 * 512; };

    // ---- fp32 -> bf16 conversions ----
    f2b_k<<<2048,  256>>>(fo, bfo);                    //  2,097,152
    f2b_k<<<4096,  256>>>(fr, bfr);                    //  4,194,304
    f2b_k<<<6144,  256>>>(Wc, bWc);                    //  6,291,456
    f2b_k<<<24576, 256>>>(Wo, bWo);                    // 25,165,824

    // ================= Stage 1: 12 projections, one launch ==============
    {
        ProjB pb{};
        const bf16* src[12] = {bfo,bfo,bfo,bfo, bfo,bfr,bfo,bfr, bfr,bfo,bfr,bfo};
        int Ms[12] = {2048,2048,2048,2048, 2048,4096,2048,4096, 4096,2048,4096,2048};
        for (int z = 0; z < 12; z++) {
            pb.A[z] = src[z];
            pb.W[z] = bWc + z * WSc;
            pb.bias[z] = bc + z * 512;
            pb.C[z] = P(z);
            pb.M[z] = Ms[z];
        }
        pb.N = 512; pb.K = 1024;
        proj_k<<<dim3(4, 32, 12), 256, SM_01>>>(pb);
    }

    GArgs g{};

    // ---- mha0 ----
    g = GArgs{P(0), P(1), S0, 2048, 2048, 128, 512, 512, 2048, 4,
              128, 128, 2048LL * 2048, 0, 0, 0, a128};
    gemm_k<0, 0, 0, 1><<<dim3(16, 16, 4), 256, SM_00>>>(g);
    softmax_k<8><<<4 * 2048, 256>>>(S0, 1, 2048);
    g = GArgs{S0, P(3), PA10, 2048, 128, 512, 2048, 512, 512, 4,
              2048LL * 2048, 128, 128, 512, 512LL * 512, 2048LL * 512, 1.f};
    gemm_k<0, 1, 2, 0><<<dim3(1, 16, 16), 256, SM_01>>>(g);
    g = GArgs{S0, P(2), PA20, 2048, 128, 512, 2048, 512, 512, 4,
              2048LL * 2048, 128, 128, 512LL * 2048, 512LL * 512, 2048LL * 512, 1.f};
    gemm_k<1, 1, 2, 0><<<dim3(1, 16, 16), 256, SM_11>>>(g);

    // ---- mha1 ----
    g = GArgs{P(4), P(5), S1, 2048, 4096, 128, 512, 512, 4096, 4,
              128, 128, 2048LL * 4096, 0, 0, 0, a128};
    gemm_k<0, 0, 0, 1><<<dim3(32, 16, 4), 256, SM_00>>>(g);
    softmax_k<16><<<4 * 2048, 256>>>(S1, 0, 2048);
    g = GArgs{S1, P(7), PA11, 2048, 128, 1024, 4096, 512, 512, 4,
              2048LL * 4096, 128, 128, 1024, 1024LL * 512, 2048LL * 512, 1.f};
    gemm_k<0, 1, 2, 0><<<dim3(1, 16, 16), 256, SM_01>>>(g);
    g = GArgs{S1, P(6), PA21, 4096, 128, 512, 4096, 512, 512, 4,
              2048LL * 4096, 128, 128, 512LL * 4096, 512LL * 512, 4096LL * 512, 1.f};
    gemm_k<1, 1, 2, 0><<<dim3(1, 32, 16), 256, SM_11>>>(g);

    // ---- mha2 ----
    g = GArgs{P(8), P(9), S2, 4096, 2048, 128, 512, 512, 2048, 4,
              128, 128, 4096LL * 2048, 0, 0, 0, a128};
    gemm_k<0, 0, 0, 1><<<dim3(16, 32, 4), 256, SM_00>>>(g);
    softmax_k<8><<<4 * 4096, 256>>>(S2, 0, 4096);
    g = GArgs{S2, P(11), PA12, 4096, 128, 512, 2048, 512, 512, 4,
              4096LL * 2048, 128, 128, 512, 512LL * 512, 4096LL * 512, 1.f};
    gemm_k<0, 1, 2, 0><<<dim3(1, 32, 16), 256, SM_01>>>(g);
    g = GArgs{S2, P(10), PA22, 2048, 128, 1024, 2048, 512, 512, 4,
              4096LL * 2048, 128, 128, 1024LL * 2048, 1024LL * 512, 2048LL * 512, 1.f};
    gemm_k<1, 1, 2, 0><<<dim3(1, 16, 16), 256, SM_11>>>(g);

    combine_obj_k<<<(N_OBJ * DIMF) / 256, 256>>>(fo, PA10, PA20, PA11, PA22, out, objb);
    combine_rel_k<<<(N_REL * DIMF) / 256, 256>>>(fr, PA12, PA21, relb);

    // ================= Stage 2: 6 projections, one launch ===============
    {
        ProjB pb{};
        const bf16* src[6] = {objb, relb, objb, relb, objb, objb};
        int widx[6] = {0, 1, 2, 4, 5, 7};
        int Ms[6]   = {2048, 4096, 2048, 4096, 2048, 2048};
        bf16* dst[6] = {q3, k3, qv3, q4, k4, kv4};
        for (int z = 0; z < 6; z++) {
            pb.A[z] = src[z];
            pb.W[z] = bWo + (long long)widx[z] * WSo;
            pb.bias[z] = bo + widx[z] * 3072;
            pb.C[z] = dst[z];
            pb.M[z] = Ms[z];
        }
        pb.N = 3072; pb.K = 1024;
        proj_k<<<dim3(24, 32, 6), 256, SM_01>>>(pb);
    }

    // ---- mha3 (only a2 used) ----
    g = GArgs{q3, k3, S, 2048, 4096, 512, 3072, 3072, 4096, 6,
              512, 512, 2048LL * 4096, 0, 0, 0, a512};
    gemm_k<0, 0, 0, 1><<<dim3(32, 16, 6), 256, SM_00>>>(g);
    softmax_k<16><<<6 * 2048, 256>>>(S, 0, 2048);
    g = GArgs{S, qv3, AH2, 4096, 512, 2048, 4096, 3072, 3072, 6,
              2048LL * 4096, 512, 512, 0, 0, 0, 1.f};
    gemm_k<1, 1, 1, 0><<<dim3(4, 32, 6), 256, SM_11>>>(g);

    // ---- mha4 (only a1 used) ----
    g = GArgs{q4, k4, S, 4096, 2048, 512, 3072, 3072, 2048, 6,
              512, 512, 4096LL * 2048, 0, 0, 0, a512};
    gemm_k<0, 0, 0, 1><<<dim3(16, 32, 6), 256, SM_00>>>(g);
    softmax_k<8><<<6 * 4096, 256>>>(S, 0, 4096);
    g = GArgs{S, kv4, AH1, 4096, 512, 2048, 2048, 3072, 3072, 6,
              4096LL * 2048, 512, 512, 0, 0, 0, 1.f};
    gemm_k<0, 1, 1, 0><<<dim3(4, 32, 6), 256, SM_01>>>(g);

    final_rel_k<<<(N_REL * DIMF) / 256, 256>>>(fr, AH1, AH2, out + (long long)N_OBJ * DIMF);
}